// round 15
// baseline (speedup 1.0000x reference)
#include <cuda_runtime.h>
#include <math.h>

typedef unsigned long long u64;

// Problem constants
#define B_   2
#define N_   2048
#define K_   48
#define XS   50     // padded smem row stride (floats)
#define D0_  64
#define D1_  64
#define H_   64
#define EIN_ 193
#define E2_  386    // 2*EIN
#define H4_  256    // 4*H

__device__ int g_mask_mode;  // 0=uint8, 1=int32, 2=float32

// Per-node rank-0 tables for GEMM1:
//   g_c0[n][o] = eb1[o] + nodes[n] . eW1[0:64, o]    (i-role)
//   g_c1[n][o] =          nodes[n] . eW1[64:128, o]  (j-role)
__device__ float g_c0[B_ * N_ * E2_];   // 6.05 MB
__device__ float g_c1[B_ * N_ * E2_];   // 6.05 MB

__global__ void detect_mask_kernel(const unsigned int* __restrict__ w) {
    bool int_ok = true, flt_ok = true;
    #pragma unroll 8
    for (int i = 0; i < 64; i++) {
        unsigned int v = w[i];
        if (v != 0u && v != 1u) int_ok = false;
        if (v != 0u && v != 0x3F800000u) flt_ok = false;
    }
    g_mask_mode = int_ok ? 1 : (flt_ok ? 2 : 0);
}

// Precompute c0/c1 for all nodes. Grid 32 x 512: block handles 128 nodes.
__global__ __launch_bounds__(512) void c01_kernel(
    const float* __restrict__ f0, const float* __restrict__ eW1,
    const float* __restrict__ eb1)
{
    __shared__ float f0s[128 * 64];   // 32 KB
    const int n0 = blockIdx.x * 128;
    const int tid = threadIdx.x;
    for (int e = tid; e < 128 * 64; e += 512) f0s[e] = f0[n0 * 64 + e];
    __syncthreads();
    const int o = tid;
    if (o < E2_) {
        float b = eb1[o];
        for (int g = 0; g < 8; g++) {
            float c0a[16], c1a[16];
            #pragma unroll
            for (int nn = 0; nn < 16; nn++) { c0a[nn] = 0.f; c1a[nn] = 0.f; }
            const float* fg = f0s + g * 16 * 64;
            for (int d = 0; d < 64; d++) {
                float w0 = eW1[d * E2_ + o];
                float w1 = eW1[(64 + d) * E2_ + o];
                #pragma unroll
                for (int nn = 0; nn < 16; nn++) {
                    float f = fg[nn * 64 + d];
                    c0a[nn] += f * w0;
                    c1a[nn] += f * w1;
                }
            }
            #pragma unroll
            for (int nn = 0; nn < 16; nn++) {
                int n = n0 + g * 16 + nn;
                g_c0[(u64)n * E2_ + o] = c0a[nn] + b;
                g_c1[(u64)n * E2_ + o] = c1a[nn];
            }
        }
    }
}

__device__ __forceinline__ float siluf(float v) {
    return v * __fdividef(1.f, 1.f + __expf(-v));
}
__device__ __forceinline__ u64 dup2(float w) {
    u64 r; asm("mov.b64 %0, {%1, %1};" : "=l"(r) : "f"(w)); return r;
}
__device__ __forceinline__ void ffma2(u64 &d, u64 a, u64 b) {
    asm("fma.rn.f32x2 %0, %1, %2, %0;" : "+l"(d) : "l"(a), "l"(b));
}
__device__ __forceinline__ u64 addf2(u64 a, u64 b) {
    u64 r; asm("add.rn.f32x2 %0, %1, %2;" : "=l"(r) : "l"(a), "l"(b)); return r;
}
__device__ __forceinline__ float2 unpk(u64 v) {
    float2 f; asm("mov.b64 {%0, %1}, %2;" : "=f"(f.x), "=f"(f.y) : "l"(v)); return f;
}

// Shared memory layout (floats), width-48 tiles, stride 50.
// Aliases: htw -> x region (x dead after GEMM1/2 phase);
//          red -> h1 region (h1 dead once GEMM2 accumulation finished).
#define OFF_NI   0          // 64
#define OFF_HTI  64         // 192
#define OFF_HNS  256        // 64
#define OFF_HNB  320        // 64
#define OFF_MSK  384        // 48
#define OFF_IDX  432        // 48 ints
#define OFF_MI   480        // 64
#define OFF_HTU  544        // 192
#define OFF_NM   736        // 128
#define OFF_HB   864        // 128
#define OFF_NO   992        // 64
#define OFF_STAT 1056       // 2
#define OFF_C0   1058       // 386 (ends 1444)
#define OFF_X    1448       // 65*50 = 3250 (64 nrm rows + rel_dist row)
#define OFF_HTW  1448       // alias: 64*50 = 3200 <= 3250
#define OFF_H1   4698       // 194*50 = 9700 (o-tile buffer)
#define OFF_RED  4698       // alias: 1536
#define OFF_M    14398      // 64*50 = 3200
#define OFF_H3   17598      // 128*50 = 6400 (g-tile buffer)
#define SMEM_FLOATS 23998   // 95,992 bytes -> 2 blocks/SM

__global__ __launch_bounds__(512, 2) void fused_kernel(
    const float* __restrict__ f0, const float* __restrict__ f1,
    const float* __restrict__ rd, const int* __restrict__ nidx,
    const unsigned char* __restrict__ nmask,
    const float* __restrict__ ln_g, const float* __restrict__ ln_b,
    const float* __restrict__ eW1,
    const float* __restrict__ eW2, const float* __restrict__ eb2,
    const float* __restrict__ hW1, const float* __restrict__ hb1,
    const float* __restrict__ hW2, const float* __restrict__ hb2,
    const float* __restrict__ nW1, const float* __restrict__ nb1,
    const float* __restrict__ nW2, const float* __restrict__ nb2,
    const float* __restrict__ hns, const float* __restrict__ hnb,
    const float* __restrict__ gW, const float* __restrict__ gb,
    float* __restrict__ out)
{
    extern __shared__ float sm[];
    const int node = blockIdx.x;
    const int base = (node >> 11) << 11;
    const int tid = threadIdx.x;

    float* ni_s  = sm + OFF_NI;
    float* hti   = sm + OFF_HTI;
    float* hns_s = sm + OFF_HNS;
    float* hnb_s = sm + OFF_HNB;
    float* msk_s = sm + OFF_MSK;
    int*   idx_s = (int*)(sm + OFF_IDX);
    float* mi_s  = sm + OFF_MI;
    float* htu_s = sm + OFF_HTU;
    float* nm    = sm + OFF_NM;
    float* hbuf  = sm + OFF_HB;
    float* no_s  = sm + OFF_NO;
    float* stat  = sm + OFF_STAT;
    float* c0_s  = sm + OFF_C0;
    float* x_s   = sm + OFF_X;
    float* htw_s = sm + OFF_HTW;
    float* h1_s  = sm + OFF_H1;
    float* red   = sm + OFF_RED;
    float* m_s   = sm + OFF_M;
    float* h3_s  = sm + OFF_H3;

    // ---- Stage 0: per-node loads ----
    if (tid < 64) {
        ni_s[tid]  = f0[node * 64 + tid];
        hns_s[tid] = hns[tid];
        hnb_s[tid] = hnb[tid];
    }
    if (tid >= 64 && tid < 256) hti[tid - 64] = f1[node * 192 + (tid - 64)];
    if (tid >= 256 && tid < 304) {
        int k = tid - 256;
        idx_s[k] = nidx[node * 48 + k];
        int mode = g_mask_mode;
        float mv;
        if (mode == 1)      mv = ((const int*)nmask)[node * 48 + k] ? 1.f : 0.f;
        else if (mode == 2) mv = ((const float*)nmask)[node * 48 + k];
        else                mv = nmask[node * 48 + k] ? 1.f : 0.f;
        msk_s[k] = mv;
    }
    if (tid < E2_) c0_s[tid] = g_c0[(u64)node * E2_ + tid];
    __syncthreads();

    // ---- Stage 1: build x rows (rel_ht_dist 64 rows + rel_dist row), all 48 k ----
    for (int e = tid; e < 48 * 64; e += 512) {
        int k = e >> 6, d = e & 63;
        int j = base + idx_s[k];
        const float* hj = f1 + j * 192 + d * 3;
        float r0 = hti[d * 3 + 0] - hj[0];
        float r1 = hti[d * 3 + 1] - hj[1];
        float r2 = hti[d * 3 + 2] - hj[2];
        x_s[d * XS + k] = sqrtf(r0 * r0 + r1 * r1 + r2 * r2);
    }
    if (tid < 48) x_s[64 * XS + tid] = rd[node * 48 + tid];
    __syncthreads();

    const int ob  = tid & 63;          // output lane (64-wide)
    const int kg6 = (tid >> 6) * 6;    // 8 k-groups x 6 k

    // ==== Fused GEMM1 -> GEMM2 over o-tiles {0:192, 192:386} ====
    u64 macc0 = 0, macc1 = 0, macc2 = 0;   // GEMM2 accumulators (h=ob, k=kg6..+5)
    #pragma unroll 1
    for (int t = 0; t < 2; t++) {
        const int obase = t * 192;
        // --- GEMM1 tile: h1[ol][k] = c0[o] + sum_i x[i][k]*eW1[128+i][o] (+c1_j, silu) ---
        // (R13 form: 1-deep weight prefetch, no deeper unroll -- fits 64-reg cap)
        {
            u64 acc[3][3];
            #pragma unroll
            for (int oi = 0; oi < 3; oi++) {
                u64 dd = dup2(c0_s[obase + ob + 64 * oi]);
                acc[oi][0] = dd; acc[oi][1] = dd; acc[oi][2] = dd;
            }
            const float* xb = x_s + kg6;
            const float* wcol = eW1 + 128 * E2_ + obase + ob;
            float wn0 = wcol[0], wn1 = wcol[64], wn2 = wcol[128];
            for (int i = 0; i < 65; i++) {
                float w0 = wn0, w1 = wn1, w2 = wn2;
                if (i < 64) {
                    const float* wr = wcol + (i + 1) * E2_;
                    wn0 = wr[0]; wn1 = wr[64]; wn2 = wr[128];
                }
                const u64* xr = (const u64*)(xb + i * XS);
                u64 a0 = xr[0], a1 = xr[1], a2 = xr[2];
                u64 wp;
                wp = dup2(w0); ffma2(acc[0][0], a0, wp); ffma2(acc[0][1], a1, wp); ffma2(acc[0][2], a2, wp);
                wp = dup2(w1); ffma2(acc[1][0], a0, wp); ffma2(acc[1][1], a1, wp); ffma2(acc[1][2], a2, wp);
                wp = dup2(w2); ffma2(acc[2][0], a0, wp); ffma2(acc[2][1], a1, wp); ffma2(acc[2][2], a2, wp);
            }
            // epilogue: add gathered c1_j, silu, store tile rows (local 0..191)
            const float* c1p[6];
            #pragma unroll
            for (int jj = 0; jj < 6; jj++)
                c1p[jj] = g_c1 + (u64)(base + idx_s[kg6 + jj]) * E2_ + obase + ob;
            #pragma unroll
            for (int oi = 0; oi < 3; oi++) {
                float* dst = h1_s + (ob + 64 * oi) * XS + kg6;
                #pragma unroll
                for (int j2 = 0; j2 < 3; j2++) {
                    float2 p = unpk(acc[oi][j2]);
                    p.x = siluf(p.x + c1p[2 * j2][64 * oi]);
                    p.y = siluf(p.y + c1p[2 * j2 + 1][64 * oi]);
                    *(float2*)(dst + 2 * j2) = p;
                }
            }
        }
        // --- mini-pass: o = 384, 385 -> tile-1 local rows 192, 193 ---
        if (t == 1 && tid < 96) {
            int o = 384 + (tid & 1);
            int k = tid >> 1;
            float a = c0_s[o];
            const float* wc = eW1 + 128 * E2_ + o;
            for (int i = 0; i < 65; i++) a += x_s[i * XS + k] * wc[i * E2_];
            a += g_c1[(u64)(base + idx_s[k]) * E2_ + o];
            h1_s[(192 + (o - 384)) * XS + k] = siluf(a);
        }
        __syncthreads();
        // --- GEMM2 accumulate this tile (h1 reads warp-broadcast; unroll 2) ---
        {
            const int R = t ? 194 : 192;
            const float* wc = eW2 + obase * 64 + ob;
            const float* hb = h1_s + kg6;
            #pragma unroll 2
            for (int ol = 0; ol < R; ol++) {
                const u64* hp = (const u64*)(hb + ol * XS);
                u64 a0 = hp[0], a1 = hp[1], a2 = hp[2];
                u64 wp = dup2(wc[ol * 64]);
                ffma2(macc0, a0, wp); ffma2(macc1, a1, wp); ffma2(macc2, a2, wp);
            }
        }
        __syncthreads();
    }
    // ---- GEMM2 epilogue: m[h][k] = silu(acc + eb2[h]); fused m_i masked partial ----
    {
        u64 bp = dup2(eb2[ob]);
        float2 p0 = unpk(addf2(macc0, bp));
        float2 p1 = unpk(addf2(macc1, bp));
        float2 p2 = unpk(addf2(macc2, bp));
        float v0 = siluf(p0.x), v1 = siluf(p0.y);
        float v2 = siluf(p1.x), v3 = siluf(p1.y);
        float v4 = siluf(p2.x), v5 = siluf(p2.y);
        float* dst = m_s + ob * XS + kg6;
        *(float2*)(dst + 0) = make_float2(v0, v1);
        *(float2*)(dst + 2) = make_float2(v2, v3);
        *(float2*)(dst + 4) = make_float2(v4, v5);
        float s = msk_s[kg6] * v0 + msk_s[kg6 + 1] * v1 + msk_s[kg6 + 2] * v2
                + msk_s[kg6 + 3] * v3 + msk_s[kg6 + 4] * v4 + msk_s[kg6 + 5] * v5;
        red[(tid >> 6) * 64 + ob] = s;   // red aliases h1 (dead)
    }
    __syncthreads();
    if (tid < 64) {
        float s = 0.f;
        #pragma unroll
        for (int kb = 0; kb < 8; kb++) s += red[kb * 64 + tid];
        mi_s[tid] = s;
    }

    // ==== Fused GEMM3 -> GEMM4 over g-tiles {0:128, 128:256} ====
    u64 wacc0 = 0, wacc1 = 0, wacc2 = 0;   // GEMM4 accumulators (d=ob, k=kg6..+5)
    #pragma unroll 1
    for (int t = 0; t < 2; t++) {
        const int gbase = t * 128;
        // --- GEMM3 tile: h3[gl][k] = silu(hb1[g] + sum_h m[h][k]*hW1[h][g]) ---
        // (R13 form: plain loop, 2 weight LDGs per body)
        {
            u64 acc[2][3];
            {
                u64 d0v = dup2(hb1[gbase + ob]);
                u64 d1v = dup2(hb1[gbase + ob + 64]);
                acc[0][0] = d0v; acc[0][1] = d0v; acc[0][2] = d0v;
                acc[1][0] = d1v; acc[1][1] = d1v; acc[1][2] = d1v;
            }
            const float* wc = hW1 + gbase + ob;
            const float* mb = m_s + kg6;
            for (int h = 0; h < 64; h++) {
                const u64* mp = (const u64*)(mb + h * XS);
                u64 a0 = mp[0], a1 = mp[1], a2 = mp[2];
                const float* wr = wc + h * H4_;
                u64 w0 = dup2(wr[0]), w1 = dup2(wr[64]);
                ffma2(acc[0][0], a0, w0); ffma2(acc[0][1], a1, w0); ffma2(acc[0][2], a2, w0);
                ffma2(acc[1][0], a0, w1); ffma2(acc[1][1], a1, w1); ffma2(acc[1][2], a2, w1);
            }
            #pragma unroll
            for (int oi = 0; oi < 2; oi++) {
                float* dst = h3_s + (ob + 64 * oi) * XS + kg6;
                #pragma unroll
                for (int j2 = 0; j2 < 3; j2++) {
                    float2 p = unpk(acc[oi][j2]);
                    *(float2*)(dst + 2 * j2) = make_float2(siluf(p.x), siluf(p.y));
                }
            }
        }
        __syncthreads();
        // --- GEMM4 accumulate this tile (unroll 2) ---
        {
            const float* wc = hW2 + gbase * 64 + ob;
            const float* hb = h3_s + kg6;
            #pragma unroll 2
            for (int gl = 0; gl < 128; gl++) {
                const u64* hp = (const u64*)(hb + gl * XS);
                u64 a0 = hp[0], a1 = hp[1], a2 = hp[2];
                u64 wp = dup2(wc[gl * 64]);
                ffma2(wacc0, a0, wp); ffma2(wacc1, a1, wp); ffma2(wacc2, a2, wp);
            }
        }
        __syncthreads();
    }
    // ---- GEMM4 epilogue: htw[d][k] = acc + hb2[d]  (htw aliases dead x) ----
    {
        u64 bp = dup2(hb2[ob]);
        u64 t0 = addf2(wacc0, bp), t1 = addf2(wacc1, bp), t2 = addf2(wacc2, bp);
        float* dst = htw_s + ob * XS + kg6;
        *(u64*)(dst + 0) = t0; *(u64*)(dst + 2) = t1; *(u64*)(dst + 4) = t2;
    }
    __syncthreads();

    // ---- ht_update einsum ----
    {
        const int d = ob;
        const int kb = tid >> 6;
        float a0 = 0.f, a1 = 0.f, a2 = 0.f;
        float sc = hns_s[d], bi = hnb_s[d];
        float h0 = hti[d * 3 + 0], h1v = hti[d * 3 + 1], h2 = hti[d * 3 + 2];
        #pragma unroll
        for (int kk = 0; kk < 6; kk++) {
            int k = kg6 + kk;
            int j = base + idx_s[k];
            const float* hj = f1 + j * 192 + d * 3;
            float r0 = h0 - hj[0];
            float r1 = h1v - hj[1];
            float r2 = h2 - hj[2];
            float nrm = sqrtf(r0 * r0 + r1 * r1 + r2 * r2);
            float coef = (nrm * sc + bi) / fmaxf(nrm, 1e-8f);
            float w = coef * htw_s[d * XS + k];
            a0 += r0 * w; a1 += r1 * w; a2 += r2 * w;
        }
        red[kb * 192 + d * 3 + 0] = a0;
        red[kb * 192 + d * 3 + 1] = a1;
        red[kb * 192 + d * 3 + 2] = a2;
    }
    __syncthreads();
    if (tid < 192) {
        float s = 0.f;
        #pragma unroll
        for (int kb = 0; kb < 8; kb++) s += red[kb * 192 + tid];
        htu_s[tid] = s;
    }
    __syncthreads();

    // ---- Node tail: LayerNorm -> MLP(128->128->64) + residual -> gate -> output ----
    if (tid < 32) {
        float s = ni_s[tid] + ni_s[tid + 32];
        #pragma unroll
        for (int off = 16; off > 0; off >>= 1) s += __shfl_xor_sync(0xffffffffu, s, off);
        if (tid == 0) stat[0] = s * (1.f / 64.f);
    }
    __syncthreads();
    if (tid < 32) {
        float mu = stat[0];
        float d0 = ni_s[tid] - mu, d1 = ni_s[tid + 32] - mu;
        float s = d0 * d0 + d1 * d1;
        #pragma unroll
        for (int off = 16; off > 0; off >>= 1) s += __shfl_xor_sync(0xffffffffu, s, off);
        if (tid == 0) stat[1] = s * (1.f / 64.f);
    }
    __syncthreads();
    if (tid < 64) {
        float mu = stat[0];
        float inv = rsqrtf(stat[1] + 1e-5f);
        nm[tid] = (ni_s[tid] - mu) * inv * ln_g[tid] + ln_b[tid];
        nm[64 + tid] = mi_s[tid];
    }
    __syncthreads();
    if (tid < 128) {
        float a = nb1[tid];
        #pragma unroll 8
        for (int e = 0; e < 128; e++) a += nm[e] * nW1[e * 128 + tid];
        hbuf[tid] = siluf(a);
    }
    __syncthreads();
    if (tid < 64) {
        float a = nb2[tid];
        #pragma unroll 8
        for (int g = 0; g < 128; g++) a += hbuf[g] * nW2[g * 64 + tid];
        no_s[tid] = a + ni_s[tid];
    }
    __syncthreads();
    if (tid < 64) {
        float a = gb[tid];
        #pragma unroll 8
        for (int e = 0; e < 64; e++) a += no_s[e] * gW[e * 64 + tid];
        float gate = __fdividef(1.f, 1.f + __expf(-a));
        int obp = node * 256 + tid * 4;
        out[obp + 0] = no_s[tid];
        #pragma unroll
        for (int m = 0; m < 3; m++)
            out[obp + 1 + m] = (hti[tid * 3 + m] + htu_s[tid * 3 + m]) * gate;
    }
}

extern "C" void kernel_launch(void* const* d_in, const int* in_sizes, int n_in,
                              void* d_out, int out_size)
{
    const float*         f0    = (const float*)d_in[0];
    const float*         f1    = (const float*)d_in[1];
    const float*         rd    = (const float*)d_in[2];
    const int*           nidx  = (const int*)d_in[3];
    const unsigned char* nmask = (const unsigned char*)d_in[4];
    const float* ln_g = (const float*)d_in[5];
    const float* ln_b = (const float*)d_in[6];
    const float* eW1  = (const float*)d_in[7];
    const float* eb1  = (const float*)d_in[8];
    const float* eW2  = (const float*)d_in[9];
    const float* eb2  = (const float*)d_in[10];
    const float* hW1  = (const float*)d_in[11];
    const float* hb1  = (const float*)d_in[12];
    const float* hW2  = (const float*)d_in[13];
    const float* hb2  = (const float*)d_in[14];
    const float* nW1  = (const float*)d_in[15];
    const float* nb1  = (const float*)d_in[16];
    const float* nW2  = (const float*)d_in[17];
    const float* nb2  = (const float*)d_in[18];
    const float* hns  = (const float*)d_in[19];
    const float* hnb  = (const float*)d_in[20];
    const float* gW   = (const float*)d_in[21];
    const float* gb   = (const float*)d_in[22];
    float* out = (float*)d_out;

    cudaFuncSetAttribute(fused_kernel, cudaFuncAttributeMaxDynamicSharedMemorySize,
                         SMEM_FLOATS * (int)sizeof(float));

    detect_mask_kernel<<<1, 1>>>((const unsigned int*)nmask);
    c01_kernel<<<(B_ * N_) / 128, 512>>>(f0, eW1, eb1);
    fused_kernel<<<B_ * N_, 512, SMEM_FLOATS * sizeof(float)>>>(
        f0, f1, rd, nidx, nmask, ln_g, ln_b, eW1, eW2, eb2, hW1, hb1, hW2, hb2,
        nW1, nb1, nW2, nb2, hns, hnb, gW, gb, out);
}

// round 16
// speedup vs baseline: 1.1405x; 1.1405x over previous
#include <cuda_runtime.h>
#include <math.h>

typedef unsigned long long u64;

// Problem constants
#define B_   2
#define N_   2048
#define K_   48
#define XS   50     // padded smem row stride (floats)
#define D0_  64
#define D1_  64
#define H_   64
#define EIN_ 193
#define E2_  386    // 2*EIN
#define H4_  256    // 4*H

__device__ int g_mask_mode;  // 0=uint8, 1=int32, 2=float32

// Per-node rank-0 tables for GEMM1:
//   g_c0[n][o] = eb1[o] + nodes[n] . eW1[0:64, o]    (i-role)
//   g_c1[n][o] =          nodes[n] . eW1[64:128, o]  (j-role)
__device__ float g_c0[B_ * N_ * E2_];   // 6.05 MB
__device__ float g_c1[B_ * N_ * E2_];   // 6.05 MB

__global__ void detect_mask_kernel(const unsigned int* __restrict__ w) {
    bool int_ok = true, flt_ok = true;
    #pragma unroll 8
    for (int i = 0; i < 64; i++) {
        unsigned int v = w[i];
        if (v != 0u && v != 1u) int_ok = false;
        if (v != 0u && v != 0x3F800000u) flt_ok = false;
    }
    g_mask_mode = int_ok ? 1 : (flt_ok ? 2 : 0);
}

// Precompute c0/c1 for all nodes. Grid 32 x 512: block handles 128 nodes.
__global__ __launch_bounds__(512) void c01_kernel(
    const float* __restrict__ f0, const float* __restrict__ eW1,
    const float* __restrict__ eb1)
{
    __shared__ float f0s[128 * 64];   // 32 KB
    const int n0 = blockIdx.x * 128;
    const int tid = threadIdx.x;
    for (int e = tid; e < 128 * 64; e += 512) f0s[e] = f0[n0 * 64 + e];
    __syncthreads();
    const int o = tid;
    if (o < E2_) {
        float b = eb1[o];
        for (int g = 0; g < 8; g++) {
            float c0a[16], c1a[16];
            #pragma unroll
            for (int nn = 0; nn < 16; nn++) { c0a[nn] = 0.f; c1a[nn] = 0.f; }
            const float* fg = f0s + g * 16 * 64;
            for (int d = 0; d < 64; d++) {
                float w0 = eW1[d * E2_ + o];
                float w1 = eW1[(64 + d) * E2_ + o];
                #pragma unroll
                for (int nn = 0; nn < 16; nn++) {
                    float f = fg[nn * 64 + d];
                    c0a[nn] += f * w0;
                    c1a[nn] += f * w1;
                }
            }
            #pragma unroll
            for (int nn = 0; nn < 16; nn++) {
                int n = n0 + g * 16 + nn;
                g_c0[(u64)n * E2_ + o] = c0a[nn] + b;
                g_c1[(u64)n * E2_ + o] = c1a[nn];
            }
        }
    }
}

__device__ __forceinline__ float siluf(float v) {
    return v * __fdividef(1.f, 1.f + __expf(-v));
}
__device__ __forceinline__ u64 dup2(float w) {
    u64 r; asm("mov.b64 %0, {%1, %1};" : "=l"(r) : "f"(w)); return r;
}
__device__ __forceinline__ void ffma2(u64 &d, u64 a, u64 b) {
    asm("fma.rn.f32x2 %0, %1, %2, %0;" : "+l"(d) : "l"(a), "l"(b));
}
__device__ __forceinline__ u64 addf2(u64 a, u64 b) {
    u64 r; asm("add.rn.f32x2 %0, %1, %2;" : "=l"(r) : "l"(a), "l"(b)); return r;
}
__device__ __forceinline__ float2 unpk(u64 v) {
    float2 f; asm("mov.b64 {%0, %1}, %2;" : "=f"(f.x), "=f"(f.y) : "l"(v)); return f;
}

// Shared memory layout (floats), width-48 tiles, stride 50.
// Aliases: htw -> x region (x dead after GEMM1/2 phase);
//          red -> h1 region (h1 dead once GEMM2 accumulation finished).
#define OFF_NI   0          // 64
#define OFF_HTI  64         // 192
#define OFF_HNS  256        // 64
#define OFF_HNB  320        // 64
#define OFF_MSK  384        // 48
#define OFF_IDX  432        // 48 ints
#define OFF_MI   480        // 64
#define OFF_HTU  544        // 192
#define OFF_NM   736        // 128
#define OFF_HB   864        // 128
#define OFF_NO   992        // 64
#define OFF_STAT 1056       // 2
#define OFF_C0   1058       // 386 (ends 1444)
#define OFF_X    1448       // 65*50 = 3250 (64 nrm rows + rel_dist row)
#define OFF_HTW  1448       // alias: 64*50 = 3200 <= 3250
#define OFF_H1   4698       // 194*50 = 9700 (o-tile buffer)
#define OFF_RED  4698       // alias: 1536
#define OFF_M    14398      // 64*50 = 3200
#define OFF_H3   17598      // 128*50 = 6400 (g-tile buffer)
#define SMEM_FLOATS 23998   // 95,992 bytes -> 2 blocks/SM

__global__ __launch_bounds__(512, 2) void fused_kernel(
    const float* __restrict__ f0, const float* __restrict__ f1,
    const float* __restrict__ rd, const int* __restrict__ nidx,
    const unsigned char* __restrict__ nmask,
    const float* __restrict__ ln_g, const float* __restrict__ ln_b,
    const float* __restrict__ eW1,
    const float* __restrict__ eW2, const float* __restrict__ eb2,
    const float* __restrict__ hW1, const float* __restrict__ hb1,
    const float* __restrict__ hW2, const float* __restrict__ hb2,
    const float* __restrict__ nW1, const float* __restrict__ nb1,
    const float* __restrict__ nW2, const float* __restrict__ nb2,
    const float* __restrict__ hns, const float* __restrict__ hnb,
    const float* __restrict__ gW, const float* __restrict__ gb,
    float* __restrict__ out)
{
    extern __shared__ float sm[];
    const int node = blockIdx.x;
    const int base = (node >> 11) << 11;
    const int tid = threadIdx.x;

    float* ni_s  = sm + OFF_NI;
    float* hti   = sm + OFF_HTI;
    float* hns_s = sm + OFF_HNS;
    float* hnb_s = sm + OFF_HNB;
    float* msk_s = sm + OFF_MSK;
    int*   idx_s = (int*)(sm + OFF_IDX);
    float* mi_s  = sm + OFF_MI;
    float* htu_s = sm + OFF_HTU;
    float* nm    = sm + OFF_NM;
    float* hbuf  = sm + OFF_HB;
    float* no_s  = sm + OFF_NO;
    float* stat  = sm + OFF_STAT;
    float* c0_s  = sm + OFF_C0;
    float* x_s   = sm + OFF_X;
    float* htw_s = sm + OFF_HTW;
    float* h1_s  = sm + OFF_H1;
    float* red   = sm + OFF_RED;
    float* m_s   = sm + OFF_M;
    float* h3_s  = sm + OFF_H3;

    // ---- Stage 0: per-node loads ----
    if (tid < 64) {
        ni_s[tid]  = f0[node * 64 + tid];
        hns_s[tid] = hns[tid];
        hnb_s[tid] = hnb[tid];
    }
    if (tid >= 64 && tid < 256) hti[tid - 64] = f1[node * 192 + (tid - 64)];
    if (tid >= 256 && tid < 304) {
        int k = tid - 256;
        idx_s[k] = nidx[node * 48 + k];
        int mode = g_mask_mode;
        float mv;
        if (mode == 1)      mv = ((const int*)nmask)[node * 48 + k] ? 1.f : 0.f;
        else if (mode == 2) mv = ((const float*)nmask)[node * 48 + k];
        else                mv = nmask[node * 48 + k] ? 1.f : 0.f;
        msk_s[k] = mv;
    }
    if (tid < E2_) c0_s[tid] = g_c0[(u64)node * E2_ + tid];
    __syncthreads();

    // ---- Stage 1: build x rows (rel_ht_dist 64 rows + rel_dist row), all 48 k ----
    for (int e = tid; e < 48 * 64; e += 512) {
        int k = e >> 6, d = e & 63;
        int j = base + idx_s[k];
        const float* hj = f1 + j * 192 + d * 3;
        float r0 = hti[d * 3 + 0] - hj[0];
        float r1 = hti[d * 3 + 1] - hj[1];
        float r2 = hti[d * 3 + 2] - hj[2];
        x_s[d * XS + k] = sqrtf(r0 * r0 + r1 * r1 + r2 * r2);
    }
    if (tid < 48) x_s[64 * XS + tid] = rd[node * 48 + tid];
    __syncthreads();

    const int ob  = tid & 63;          // output lane (64-wide)
    const int kg6 = (tid >> 6) * 6;    // 8 k-groups x 6 k

    // ==== Fused GEMM1 -> GEMM2 over o-tiles {0:192, 192:386} ====
    u64 macc0 = 0, macc1 = 0, macc2 = 0;   // GEMM2 accumulators (h=ob, k=kg6..+5)
    #pragma unroll 1
    for (int t = 0; t < 2; t++) {
        const int obase = t * 192;
        // --- GEMM1 tile: h1[ol][k] = c0[o] + sum_i x[i][k]*eW1[128+i][o] (+c1_j, silu) ---
        // (R13 form: 1-deep weight prefetch)
        {
            u64 acc[3][3];
            #pragma unroll
            for (int oi = 0; oi < 3; oi++) {
                u64 dd = dup2(c0_s[obase + ob + 64 * oi]);
                acc[oi][0] = dd; acc[oi][1] = dd; acc[oi][2] = dd;
            }
            const float* xb = x_s + kg6;
            const float* wcol = eW1 + 128 * E2_ + obase + ob;
            float wn0 = wcol[0], wn1 = wcol[64], wn2 = wcol[128];
            for (int i = 0; i < 65; i++) {
                float w0 = wn0, w1 = wn1, w2 = wn2;
                if (i < 64) {
                    const float* wr = wcol + (i + 1) * E2_;
                    wn0 = wr[0]; wn1 = wr[64]; wn2 = wr[128];
                }
                const u64* xr = (const u64*)(xb + i * XS);
                u64 a0 = xr[0], a1 = xr[1], a2 = xr[2];
                u64 wp;
                wp = dup2(w0); ffma2(acc[0][0], a0, wp); ffma2(acc[0][1], a1, wp); ffma2(acc[0][2], a2, wp);
                wp = dup2(w1); ffma2(acc[1][0], a0, wp); ffma2(acc[1][1], a1, wp); ffma2(acc[1][2], a2, wp);
                wp = dup2(w2); ffma2(acc[2][0], a0, wp); ffma2(acc[2][1], a1, wp); ffma2(acc[2][2], a2, wp);
            }
            // epilogue: add gathered c1_j, silu, store tile rows (local 0..191)
            const float* c1p[6];
            #pragma unroll
            for (int jj = 0; jj < 6; jj++)
                c1p[jj] = g_c1 + (u64)(base + idx_s[kg6 + jj]) * E2_ + obase + ob;
            #pragma unroll
            for (int oi = 0; oi < 3; oi++) {
                float* dst = h1_s + (ob + 64 * oi) * XS + kg6;
                #pragma unroll
                for (int j2 = 0; j2 < 3; j2++) {
                    float2 p = unpk(acc[oi][j2]);
                    p.x = siluf(p.x + c1p[2 * j2][64 * oi]);
                    p.y = siluf(p.y + c1p[2 * j2 + 1][64 * oi]);
                    *(float2*)(dst + 2 * j2) = p;
                }
            }
        }
        // --- mini-pass: o = 384, 385 -> tile-1 local rows 192, 193 ---
        if (t == 1 && tid < 96) {
            int o = 384 + (tid & 1);
            int k = tid >> 1;
            float a = c0_s[o];
            const float* wc = eW1 + 128 * E2_ + o;
            for (int i = 0; i < 65; i++) a += x_s[i * XS + k] * wc[i * E2_];
            a += g_c1[(u64)(base + idx_s[k]) * E2_ + o];
            h1_s[(192 + (o - 384)) * XS + k] = siluf(a);
        }
        __syncthreads();
        // --- GEMM2 accumulate this tile (h1 reads warp-broadcast; 1-deep weight prefetch) ---
        {
            const int R = t ? 194 : 192;
            const float* wc = eW2 + obase * 64 + ob;
            const float* hb = h1_s + kg6;
            float wnext = wc[0];
            for (int ol = 0; ol < R; ol++) {
                float w = wnext;
                if (ol + 1 < R) wnext = wc[(ol + 1) * 64];
                const u64* hp = (const u64*)(hb + ol * XS);
                u64 a0 = hp[0], a1 = hp[1], a2 = hp[2];
                u64 wp = dup2(w);
                ffma2(macc0, a0, wp); ffma2(macc1, a1, wp); ffma2(macc2, a2, wp);
            }
        }
        __syncthreads();
    }
    // ---- GEMM2 epilogue: m[h][k] = silu(acc + eb2[h]) ----
    {
        u64 bp = dup2(eb2[ob]);
        u64 t0 = addf2(macc0, bp), t1 = addf2(macc1, bp), t2 = addf2(macc2, bp);
        float* dst = m_s + ob * XS + kg6;
        float2 p;
        p = unpk(t0); *(float2*)(dst + 0) = make_float2(siluf(p.x), siluf(p.y));
        p = unpk(t1); *(float2*)(dst + 2) = make_float2(siluf(p.x), siluf(p.y));
        p = unpk(t2); *(float2*)(dst + 4) = make_float2(siluf(p.x), siluf(p.y));
    }
    __syncthreads();

    // ---- m_i partials (masked sum over k) -> red (aliases dead h1) ----
    {
        float s = 0.f;
        #pragma unroll
        for (int kk = 0; kk < 6; kk++) s += msk_s[kg6 + kk] * m_s[ob * XS + kg6 + kk];
        red[(tid >> 6) * 64 + ob] = s;
    }
    __syncthreads();
    if (tid < 64) {
        float s = 0.f;
        #pragma unroll
        for (int kb = 0; kb < 8; kb++) s += red[kb * 64 + tid];
        mi_s[tid] = s;
    }

    // ==== Fused GEMM3 -> GEMM4 over g-tiles {0:128, 128:256} ====
    u64 wacc0 = 0, wacc1 = 0, wacc2 = 0;   // GEMM4 accumulators (d=ob, k=kg6..+5)
    #pragma unroll 1
    for (int t = 0; t < 2; t++) {
        const int gbase = t * 128;
        // --- GEMM3 tile: h3[gl][k] = silu(hb1[g] + sum_h m[h][k]*hW1[h][g]) ---
        // (R13 form: plain loop, 2 weight LDGs per body)
        {
            u64 acc[2][3];
            {
                u64 d0v = dup2(hb1[gbase + ob]);
                u64 d1v = dup2(hb1[gbase + ob + 64]);
                acc[0][0] = d0v; acc[0][1] = d0v; acc[0][2] = d0v;
                acc[1][0] = d1v; acc[1][1] = d1v; acc[1][2] = d1v;
            }
            const float* wc = hW1 + gbase + ob;
            const float* mb = m_s + kg6;
            for (int h = 0; h < 64; h++) {
                const u64* mp = (const u64*)(mb + h * XS);
                u64 a0 = mp[0], a1 = mp[1], a2 = mp[2];
                const float* wr = wc + h * H4_;
                u64 w0 = dup2(wr[0]), w1 = dup2(wr[64]);
                ffma2(acc[0][0], a0, w0); ffma2(acc[0][1], a1, w0); ffma2(acc[0][2], a2, w0);
                ffma2(acc[1][0], a0, w1); ffma2(acc[1][1], a1, w1); ffma2(acc[1][2], a2, w1);
            }
            #pragma unroll
            for (int oi = 0; oi < 2; oi++) {
                float* dst = h3_s + (ob + 64 * oi) * XS + kg6;
                #pragma unroll
                for (int j2 = 0; j2 < 3; j2++) {
                    float2 p = unpk(acc[oi][j2]);
                    *(float2*)(dst + 2 * j2) = make_float2(siluf(p.x), siluf(p.y));
                }
            }
        }
        __syncthreads();
        // --- GEMM4 accumulate this tile (1-deep weight prefetch) ---
        {
            const float* wc = hW2 + gbase * 64 + ob;
            const float* hb = h3_s + kg6;
            float wnext = wc[0];
            for (int gl = 0; gl < 128; gl++) {
                float w = wnext;
                if (gl + 1 < 128) wnext = wc[(gl + 1) * 64];
                const u64* hp = (const u64*)(hb + gl * XS);
                u64 a0 = hp[0], a1 = hp[1], a2 = hp[2];
                u64 wp = dup2(w);
                ffma2(wacc0, a0, wp); ffma2(wacc1, a1, wp); ffma2(wacc2, a2, wp);
            }
        }
        __syncthreads();
    }
    // ---- GEMM4 epilogue: htw[d][k] = acc + hb2[d]  (htw aliases dead x) ----
    {
        u64 bp = dup2(hb2[ob]);
        u64 t0 = addf2(wacc0, bp), t1 = addf2(wacc1, bp), t2 = addf2(wacc2, bp);
        float* dst = htw_s + ob * XS + kg6;
        *(u64*)(dst + 0) = t0; *(u64*)(dst + 2) = t1; *(u64*)(dst + 4) = t2;
    }
    __syncthreads();

    // ---- ht_update einsum ----
    {
        const int d = ob;
        const int kb = tid >> 6;
        float a0 = 0.f, a1 = 0.f, a2 = 0.f;
        float sc = hns_s[d], bi = hnb_s[d];
        float h0 = hti[d * 3 + 0], h1v = hti[d * 3 + 1], h2 = hti[d * 3 + 2];
        #pragma unroll
        for (int kk = 0; kk < 6; kk++) {
            int k = kg6 + kk;
            int j = base + idx_s[k];
            const float* hj = f1 + j * 192 + d * 3;
            float r0 = h0 - hj[0];
            float r1 = h1v - hj[1];
            float r2 = h2 - hj[2];
            float nrm = sqrtf(r0 * r0 + r1 * r1 + r2 * r2);
            float coef = (nrm * sc + bi) / fmaxf(nrm, 1e-8f);
            float w = coef * htw_s[d * XS + k];
            a0 += r0 * w; a1 += r1 * w; a2 += r2 * w;
        }
        red[kb * 192 + d * 3 + 0] = a0;
        red[kb * 192 + d * 3 + 1] = a1;
        red[kb * 192 + d * 3 + 2] = a2;
    }
    __syncthreads();
    if (tid < 192) {
        float s = 0.f;
        #pragma unroll
        for (int kb = 0; kb < 8; kb++) s += red[kb * 192 + tid];
        htu_s[tid] = s;
    }
    __syncthreads();

    // ---- Node tail: LayerNorm -> MLP(128->128->64) + residual -> gate -> output ----
    if (tid < 32) {
        float s = ni_s[tid] + ni_s[tid + 32];
        #pragma unroll
        for (int off = 16; off > 0; off >>= 1) s += __shfl_xor_sync(0xffffffffu, s, off);
        if (tid == 0) stat[0] = s * (1.f / 64.f);
    }
    __syncthreads();
    if (tid < 32) {
        float mu = stat[0];
        float d0 = ni_s[tid] - mu, d1 = ni_s[tid + 32] - mu;
        float s = d0 * d0 + d1 * d1;
        #pragma unroll
        for (int off = 16; off > 0; off >>= 1) s += __shfl_xor_sync(0xffffffffu, s, off);
        if (tid == 0) stat[1] = s * (1.f / 64.f);
    }
    __syncthreads();
    if (tid < 64) {
        float mu = stat[0];
        float inv = rsqrtf(stat[1] + 1e-5f);
        nm[tid] = (ni_s[tid] - mu) * inv * ln_g[tid] + ln_b[tid];
        nm[64 + tid] = mi_s[tid];
    }
    __syncthreads();
    if (tid < 128) {
        float a = nb1[tid];
        #pragma unroll 8
        for (int e = 0; e < 128; e++) a += nm[e] * nW1[e * 128 + tid];
        hbuf[tid] = siluf(a);
    }
    __syncthreads();
    if (tid < 64) {
        float a = nb2[tid];
        #pragma unroll 8
        for (int g = 0; g < 128; g++) a += hbuf[g] * nW2[g * 64 + tid];
        no_s[tid] = a + ni_s[tid];
    }
    __syncthreads();
    if (tid < 64) {
        float a = gb[tid];
        #pragma unroll 8
        for (int e = 0; e < 64; e++) a += no_s[e] * gW[e * 64 + tid];
        float gate = __fdividef(1.f, 1.f + __expf(-a));
        int obp = node * 256 + tid * 4;
        out[obp + 0] = no_s[tid];
        #pragma unroll
        for (int m = 0; m < 3; m++)
            out[obp + 1 + m] = (hti[tid * 3 + m] + htu_s[tid * 3 + m]) * gate;
    }
}

extern "C" void kernel_launch(void* const* d_in, const int* in_sizes, int n_in,
                              void* d_out, int out_size)
{
    const float*         f0    = (const float*)d_in[0];
    const float*         f1    = (const float*)d_in[1];
    const float*         rd    = (const float*)d_in[2];
    const int*           nidx  = (const int*)d_in[3];
    const unsigned char* nmask = (const unsigned char*)d_in[4];
    const float* ln_g = (const float*)d_in[5];
    const float* ln_b = (const float*)d_in[6];
    const float* eW1  = (const float*)d_in[7];
    const float* eb1  = (const float*)d_in[8];
    const float* eW2  = (const float*)d_in[9];
    const float* eb2  = (const float*)d_in[10];
    const float* hW1  = (const float*)d_in[11];
    const float* hb1  = (const float*)d_in[12];
    const float* hW2  = (const float*)d_in[13];
    const float* hb2  = (const float*)d_in[14];
    const float* nW1  = (const float*)d_in[15];
    const float* nb1  = (const float*)d_in[16];
    const float* nW2  = (const float*)d_in[17];
    const float* nb2  = (const float*)d_in[18];
    const float* hns  = (const float*)d_in[19];
    const float* hnb  = (const float*)d_in[20];
    const float* gW   = (const float*)d_in[21];
    const float* gb   = (const float*)d_in[22];
    float* out = (float*)d_out;

    cudaFuncSetAttribute(fused_kernel, cudaFuncAttributeMaxDynamicSharedMemorySize,
                         SMEM_FLOATS * (int)sizeof(float));

    detect_mask_kernel<<<1, 1>>>((const unsigned int*)nmask);
    c01_kernel<<<(B_ * N_) / 128, 512>>>(f0, eW1, eb1);
    fused_kernel<<<B_ * N_, 512, SMEM_FLOATS * sizeof(float)>>>(
        f0, f1, rd, nidx, nmask, ln_g, ln_b, eW1, eW2, eb2, hW1, hb1, hW2, hb2,
        nW1, nb1, nW2, nb2, hns, hnb, gW, gb, out);
}

// round 17
// speedup vs baseline: 1.1434x; 1.0026x over previous
#include <cuda_runtime.h>
#include <math.h>

typedef unsigned long long u64;

// Problem constants
#define B_   2
#define N_   2048
#define K_   48
#define XS   50     // padded smem row stride (floats)
#define D0_  64
#define D1_  64
#define H_   64
#define EIN_ 193
#define E2_  386    // 2*EIN
#define H4_  256    // 4*H

__device__ int g_mask_mode;  // 0=uint8, 1=int32, 2=float32

// Per-node rank-0 tables for GEMM1:
//   g_c0[n][o] = eb1[o] + nodes[n] . eW1[0:64, o]    (i-role)
//   g_c1[n][o] =          nodes[n] . eW1[64:128, o]  (j-role)
__device__ float g_c0[B_ * N_ * E2_];   // 6.05 MB
__device__ float g_c1[B_ * N_ * E2_];   // 6.05 MB

__global__ void detect_mask_kernel(const unsigned int* __restrict__ w) {
    bool int_ok = true, flt_ok = true;
    #pragma unroll 8
    for (int i = 0; i < 64; i++) {
        unsigned int v = w[i];
        if (v != 0u && v != 1u) int_ok = false;
        if (v != 0u && v != 0x3F800000u) flt_ok = false;
    }
    g_mask_mode = int_ok ? 1 : (flt_ok ? 2 : 0);
}

// Precompute c0/c1 for all nodes. Grid 32 x 512: block handles 128 nodes.
__global__ __launch_bounds__(512) void c01_kernel(
    const float* __restrict__ f0, const float* __restrict__ eW1,
    const float* __restrict__ eb1)
{
    __shared__ float f0s[128 * 64];   // 32 KB
    const int n0 = blockIdx.x * 128;
    const int tid = threadIdx.x;
    for (int e = tid; e < 128 * 64; e += 512) f0s[e] = f0[n0 * 64 + e];
    __syncthreads();
    const int o = tid;
    if (o < E2_) {
        float b = eb1[o];
        for (int g = 0; g < 8; g++) {
            float c0a[16], c1a[16];
            #pragma unroll
            for (int nn = 0; nn < 16; nn++) { c0a[nn] = 0.f; c1a[nn] = 0.f; }
            const float* fg = f0s + g * 16 * 64;
            for (int d = 0; d < 64; d++) {
                float w0 = eW1[d * E2_ + o];
                float w1 = eW1[(64 + d) * E2_ + o];
                #pragma unroll
                for (int nn = 0; nn < 16; nn++) {
                    float f = fg[nn * 64 + d];
                    c0a[nn] += f * w0;
                    c1a[nn] += f * w1;
                }
            }
            #pragma unroll
            for (int nn = 0; nn < 16; nn++) {
                int n = n0 + g * 16 + nn;
                g_c0[(u64)n * E2_ + o] = c0a[nn] + b;
                g_c1[(u64)n * E2_ + o] = c1a[nn];
            }
        }
    }
}

__device__ __forceinline__ float siluf(float v) {
    return v * __fdividef(1.f, 1.f + __expf(-v));
}
__device__ __forceinline__ u64 dup2(float w) {
    u64 r; asm("mov.b64 %0, {%1, %1};" : "=l"(r) : "f"(w)); return r;
}
__device__ __forceinline__ void ffma2(u64 &d, u64 a, u64 b) {
    asm("fma.rn.f32x2 %0, %1, %2, %0;" : "+l"(d) : "l"(a), "l"(b));
}
__device__ __forceinline__ u64 addf2(u64 a, u64 b) {
    u64 r; asm("add.rn.f32x2 %0, %1, %2;" : "=l"(r) : "l"(a), "l"(b)); return r;
}
__device__ __forceinline__ float2 unpk(u64 v) {
    float2 f; asm("mov.b64 {%0, %1}, %2;" : "=f"(f.x), "=f"(f.y) : "l"(v)); return f;
}

// Shared memory layout (floats), width-48 tiles, stride 50.
// Aliases: htw -> x region (x dead after GEMM1/2 phase);
//          red -> h1 region (h1 dead once GEMM2 accumulation finished).
#define OFF_NI   0          // 64
#define OFF_HTI  64         // 192
#define OFF_HNS  256        // 64
#define OFF_HNB  320        // 64
#define OFF_MSK  384        // 48
#define OFF_IDX  432        // 48 ints
#define OFF_MI   480        // 64
#define OFF_HTU  544        // 192
#define OFF_NM   736        // 128
#define OFF_HB   864        // 128
#define OFF_NO   992        // 64
#define OFF_STAT 1056       // 2
#define OFF_C0   1058       // 386 (ends 1444)
#define OFF_X    1448       // 65*50 = 3250 (64 nrm rows + rel_dist row)
#define OFF_HTW  1448       // alias: 64*50 = 3200 <= 3250
#define OFF_H1   4698       // 194*50 = 9700 (o-tile buffer)
#define OFF_RED  4698       // alias: 1536
#define OFF_M    14398      // 64*50 = 3200
#define OFF_H3   17598      // 128*50 = 6400 (g-tile buffer)
#define SMEM_FLOATS 23998   // 95,992 bytes -> 2 blocks/SM

__global__ __launch_bounds__(512, 2) void fused_kernel(
    const float* __restrict__ f0, const float* __restrict__ f1,
    const float* __restrict__ rd, const int* __restrict__ nidx,
    const unsigned char* __restrict__ nmask,
    const float* __restrict__ ln_g, const float* __restrict__ ln_b,
    const float* __restrict__ eW1,
    const float* __restrict__ eW2, const float* __restrict__ eb2,
    const float* __restrict__ hW1, const float* __restrict__ hb1,
    const float* __restrict__ hW2, const float* __restrict__ hb2,
    const float* __restrict__ nW1, const float* __restrict__ nb1,
    const float* __restrict__ nW2, const float* __restrict__ nb2,
    const float* __restrict__ hns, const float* __restrict__ hnb,
    const float* __restrict__ gW, const float* __restrict__ gb,
    float* __restrict__ out)
{
    extern __shared__ float sm[];
    const int node = blockIdx.x;
    const int base = (node >> 11) << 11;
    const int tid = threadIdx.x;

    float* ni_s  = sm + OFF_NI;
    float* hti   = sm + OFF_HTI;
    float* hns_s = sm + OFF_HNS;
    float* hnb_s = sm + OFF_HNB;
    float* msk_s = sm + OFF_MSK;
    int*   idx_s = (int*)(sm + OFF_IDX);
    float* mi_s  = sm + OFF_MI;
    float* htu_s = sm + OFF_HTU;
    float* nm    = sm + OFF_NM;
    float* hbuf  = sm + OFF_HB;
    float* no_s  = sm + OFF_NO;
    float* stat  = sm + OFF_STAT;
    float* c0_s  = sm + OFF_C0;
    float* x_s   = sm + OFF_X;
    float* htw_s = sm + OFF_HTW;
    float* h1_s  = sm + OFF_H1;
    float* red   = sm + OFF_RED;
    float* m_s   = sm + OFF_M;
    float* h3_s  = sm + OFF_H3;

    // ---- Stage 0: per-node loads ----
    if (tid < 64) {
        ni_s[tid]  = f0[node * 64 + tid];
        hns_s[tid] = hns[tid];
        hnb_s[tid] = hnb[tid];
    }
    if (tid >= 64 && tid < 256) hti[tid - 64] = f1[node * 192 + (tid - 64)];
    if (tid >= 256 && tid < 304) {
        int k = tid - 256;
        idx_s[k] = nidx[node * 48 + k];
        int mode = g_mask_mode;
        float mv;
        if (mode == 1)      mv = ((const int*)nmask)[node * 48 + k] ? 1.f : 0.f;
        else if (mode == 2) mv = ((const float*)nmask)[node * 48 + k];
        else                mv = nmask[node * 48 + k] ? 1.f : 0.f;
        msk_s[k] = mv;
    }
    if (tid < E2_) c0_s[tid] = g_c0[(u64)node * E2_ + tid];
    __syncthreads();

    // ---- Stage 1: build x rows (rel_ht_dist 64 rows + rel_dist row), all 48 k ----
    for (int e = tid; e < 48 * 64; e += 512) {
        int k = e >> 6, d = e & 63;
        int j = base + idx_s[k];
        const float* hj = f1 + j * 192 + d * 3;
        float r0 = hti[d * 3 + 0] - hj[0];
        float r1 = hti[d * 3 + 1] - hj[1];
        float r2 = hti[d * 3 + 2] - hj[2];
        x_s[d * XS + k] = sqrtf(r0 * r0 + r1 * r1 + r2 * r2);
    }
    if (tid < 48) x_s[64 * XS + tid] = rd[node * 48 + tid];
    __syncthreads();

    const int ob  = tid & 63;          // output lane (64-wide)
    const int kg6 = (tid >> 6) * 6;    // 8 k-groups x 6 k

    // ==== Fused GEMM1 -> GEMM2 over o-tiles {0:192, 192:386} ====
    u64 macc0 = 0, macc1 = 0, macc2 = 0;   // GEMM2 accumulators (h=ob, k=kg6..+5)
    #pragma unroll 1
    for (int t = 0; t < 2; t++) {
        const int obase = t * 192;
        // --- GEMM1 tile: h1[ol][k] = c0[o] + sum_i x[i][k]*eW1[128+i][o] (+c1_j, silu) ---
        // (1-deep weight prefetch)
        {
            u64 acc[3][3];
            #pragma unroll
            for (int oi = 0; oi < 3; oi++) {
                u64 dd = dup2(c0_s[obase + ob + 64 * oi]);
                acc[oi][0] = dd; acc[oi][1] = dd; acc[oi][2] = dd;
            }
            const float* xb = x_s + kg6;
            const float* wcol = eW1 + 128 * E2_ + obase + ob;
            float wn0 = wcol[0], wn1 = wcol[64], wn2 = wcol[128];
            for (int i = 0; i < 65; i++) {
                float w0 = wn0, w1 = wn1, w2 = wn2;
                if (i < 64) {
                    const float* wr = wcol + (i + 1) * E2_;
                    wn0 = wr[0]; wn1 = wr[64]; wn2 = wr[128];
                }
                const u64* xr = (const u64*)(xb + i * XS);
                u64 a0 = xr[0], a1 = xr[1], a2 = xr[2];
                u64 wp;
                wp = dup2(w0); ffma2(acc[0][0], a0, wp); ffma2(acc[0][1], a1, wp); ffma2(acc[0][2], a2, wp);
                wp = dup2(w1); ffma2(acc[1][0], a0, wp); ffma2(acc[1][1], a1, wp); ffma2(acc[1][2], a2, wp);
                wp = dup2(w2); ffma2(acc[2][0], a0, wp); ffma2(acc[2][1], a1, wp); ffma2(acc[2][2], a2, wp);
            }
            // epilogue: add gathered c1_j, silu, store tile rows (local 0..191)
            const float* c1p[6];
            #pragma unroll
            for (int jj = 0; jj < 6; jj++)
                c1p[jj] = g_c1 + (u64)(base + idx_s[kg6 + jj]) * E2_ + obase + ob;
            #pragma unroll
            for (int oi = 0; oi < 3; oi++) {
                float* dst = h1_s + (ob + 64 * oi) * XS + kg6;
                #pragma unroll
                for (int j2 = 0; j2 < 3; j2++) {
                    float2 p = unpk(acc[oi][j2]);
                    p.x = siluf(p.x + c1p[2 * j2][64 * oi]);
                    p.y = siluf(p.y + c1p[2 * j2 + 1][64 * oi]);
                    *(float2*)(dst + 2 * j2) = p;
                }
            }
        }
        // --- mini-pass: o = 384, 385 -> tile-1 local rows 192, 193 ---
        if (t == 1 && tid < 96) {
            int o = 384 + (tid & 1);
            int k = tid >> 1;
            float a = c0_s[o];
            const float* wc = eW1 + 128 * E2_ + o;
            for (int i = 0; i < 65; i++) a += x_s[i * XS + k] * wc[i * E2_];
            a += g_c1[(u64)(base + idx_s[k]) * E2_ + o];
            h1_s[(192 + (o - 384)) * XS + k] = siluf(a);
        }
        __syncthreads();
        // --- GEMM2 accumulate this tile (h1 reads warp-broadcast; 1-deep weight prefetch) ---
        {
            const int R = t ? 194 : 192;
            const float* wc = eW2 + obase * 64 + ob;
            const float* hb = h1_s + kg6;
            float wnext = wc[0];
            for (int ol = 0; ol < R; ol++) {
                float w = wnext;
                if (ol + 1 < R) wnext = wc[(ol + 1) * 64];
                const u64* hp = (const u64*)(hb + ol * XS);
                u64 a0 = hp[0], a1 = hp[1], a2 = hp[2];
                u64 wp = dup2(w);
                ffma2(macc0, a0, wp); ffma2(macc1, a1, wp); ffma2(macc2, a2, wp);
            }
        }
        __syncthreads();
    }
    // ---- GEMM2 epilogue: m[h][k] = silu(acc + eb2[h]) ----
    {
        u64 bp = dup2(eb2[ob]);
        u64 t0 = addf2(macc0, bp), t1 = addf2(macc1, bp), t2 = addf2(macc2, bp);
        float* dst = m_s + ob * XS + kg6;
        float2 p;
        p = unpk(t0); *(float2*)(dst + 0) = make_float2(siluf(p.x), siluf(p.y));
        p = unpk(t1); *(float2*)(dst + 2) = make_float2(siluf(p.x), siluf(p.y));
        p = unpk(t2); *(float2*)(dst + 4) = make_float2(siluf(p.x), siluf(p.y));
    }
    __syncthreads();

    // ---- m_i partials (masked sum over k) -> red (aliases dead h1) ----
    {
        float s = 0.f;
        #pragma unroll
        for (int kk = 0; kk < 6; kk++) s += msk_s[kg6 + kk] * m_s[ob * XS + kg6 + kk];
        red[(tid >> 6) * 64 + ob] = s;
    }
    __syncthreads();
    if (tid < 64) {
        float s = 0.f;
        #pragma unroll
        for (int kb = 0; kb < 8; kb++) s += red[kb * 64 + tid];
        mi_s[tid] = s;
    }

    // ==== Fused GEMM3 -> GEMM4 over g-tiles {0:128, 128:256} ====
    u64 wacc0 = 0, wacc1 = 0, wacc2 = 0;   // GEMM4 accumulators (d=ob, k=kg6..+5)
    #pragma unroll 1
    for (int t = 0; t < 2; t++) {
        const int gbase = t * 128;
        // --- GEMM3 tile: h3[gl][k] = silu(hb1[g] + sum_h m[h][k]*hW1[h][g]) ---
        // (1-deep weight prefetch -- same pattern as GEMM1/2/4)
        {
            u64 acc[2][3];
            {
                u64 d0v = dup2(hb1[gbase + ob]);
                u64 d1v = dup2(hb1[gbase + ob + 64]);
                acc[0][0] = d0v; acc[0][1] = d0v; acc[0][2] = d0v;
                acc[1][0] = d1v; acc[1][1] = d1v; acc[1][2] = d1v;
            }
            const float* wc = hW1 + gbase + ob;
            const float* mb = m_s + kg6;
            float wn0 = wc[0], wn1 = wc[64];
            for (int h = 0; h < 64; h++) {
                float w0f = wn0, w1f = wn1;
                if (h + 1 < 64) {
                    const float* wr = wc + (h + 1) * H4_;
                    wn0 = wr[0]; wn1 = wr[64];
                }
                const u64* mp = (const u64*)(mb + h * XS);
                u64 a0 = mp[0], a1 = mp[1], a2 = mp[2];
                u64 w0 = dup2(w0f), w1 = dup2(w1f);
                ffma2(acc[0][0], a0, w0); ffma2(acc[0][1], a1, w0); ffma2(acc[0][2], a2, w0);
                ffma2(acc[1][0], a0, w1); ffma2(acc[1][1], a1, w1); ffma2(acc[1][2], a2, w1);
            }
            #pragma unroll
            for (int oi = 0; oi < 2; oi++) {
                float* dst = h3_s + (ob + 64 * oi) * XS + kg6;
                #pragma unroll
                for (int j2 = 0; j2 < 3; j2++) {
                    float2 p = unpk(acc[oi][j2]);
                    *(float2*)(dst + 2 * j2) = make_float2(siluf(p.x), siluf(p.y));
                }
            }
        }
        __syncthreads();
        // --- GEMM4 accumulate this tile (1-deep weight prefetch) ---
        {
            const float* wc = hW2 + gbase * 64 + ob;
            const float* hb = h3_s + kg6;
            float wnext = wc[0];
            for (int gl = 0; gl < 128; gl++) {
                float w = wnext;
                if (gl + 1 < 128) wnext = wc[(gl + 1) * 64];
                const u64* hp = (const u64*)(hb + gl * XS);
                u64 a0 = hp[0], a1 = hp[1], a2 = hp[2];
                u64 wp = dup2(w);
                ffma2(wacc0, a0, wp); ffma2(wacc1, a1, wp); ffma2(wacc2, a2, wp);
            }
        }
        __syncthreads();
    }
    // ---- GEMM4 epilogue: htw[d][k] = acc + hb2[d]  (htw aliases dead x) ----
    {
        u64 bp = dup2(hb2[ob]);
        u64 t0 = addf2(wacc0, bp), t1 = addf2(wacc1, bp), t2 = addf2(wacc2, bp);
        float* dst = htw_s + ob * XS + kg6;
        *(u64*)(dst + 0) = t0; *(u64*)(dst + 2) = t1; *(u64*)(dst + 4) = t2;
    }
    __syncthreads();

    // ---- ht_update einsum ----
    {
        const int d = ob;
        const int kb = tid >> 6;
        float a0 = 0.f, a1 = 0.f, a2 = 0.f;
        float sc = hns_s[d], bi = hnb_s[d];
        float h0 = hti[d * 3 + 0], h1v = hti[d * 3 + 1], h2 = hti[d * 3 + 2];
        #pragma unroll
        for (int kk = 0; kk < 6; kk++) {
            int k = kg6 + kk;
            int j = base + idx_s[k];
            const float* hj = f1 + j * 192 + d * 3;
            float r0 = h0 - hj[0];
            float r1 = h1v - hj[1];
            float r2 = h2 - hj[2];
            float nrm = sqrtf(r0 * r0 + r1 * r1 + r2 * r2);
            float coef = (nrm * sc + bi) / fmaxf(nrm, 1e-8f);
            float w = coef * htw_s[d * XS + k];
            a0 += r0 * w; a1 += r1 * w; a2 += r2 * w;
        }
        red[kb * 192 + d * 3 + 0] = a0;
        red[kb * 192 + d * 3 + 1] = a1;
        red[kb * 192 + d * 3 + 2] = a2;
    }
    __syncthreads();
    if (tid < 192) {
        float s = 0.f;
        #pragma unroll
        for (int kb = 0; kb < 8; kb++) s += red[kb * 192 + tid];
        htu_s[tid] = s;
    }
    __syncthreads();

    // ---- Node tail: LayerNorm -> MLP(128->128->64) + residual -> gate -> output ----
    if (tid < 32) {
        float s = ni_s[tid] + ni_s[tid + 32];
        #pragma unroll
        for (int off = 16; off > 0; off >>= 1) s += __shfl_xor_sync(0xffffffffu, s, off);
        if (tid == 0) stat[0] = s * (1.f / 64.f);
    }
    __syncthreads();
    if (tid < 32) {
        float mu = stat[0];
        float d0 = ni_s[tid] - mu, d1 = ni_s[tid + 32] - mu;
        float s = d0 * d0 + d1 * d1;
        #pragma unroll
        for (int off = 16; off > 0; off >>= 1) s += __shfl_xor_sync(0xffffffffu, s, off);
        if (tid == 0) stat[1] = s * (1.f / 64.f);
    }
    __syncthreads();
    if (tid < 64) {
        float mu = stat[0];
        float inv = rsqrtf(stat[1] + 1e-5f);
        nm[tid] = (ni_s[tid] - mu) * inv * ln_g[tid] + ln_b[tid];
        nm[64 + tid] = mi_s[tid];
    }
    __syncthreads();
    if (tid < 128) {
        float a = nb1[tid];
        #pragma unroll 8
        for (int e = 0; e < 128; e++) a += nm[e] * nW1[e * 128 + tid];
        hbuf[tid] = siluf(a);
    }
    __syncthreads();
    if (tid < 64) {
        float a = nb2[tid];
        #pragma unroll 8
        for (int g = 0; g < 128; g++) a += hbuf[g] * nW2[g * 64 + tid];
        no_s[tid] = a + ni_s[tid];
    }
    __syncthreads();
    if (tid < 64) {
        float a = gb[tid];
        #pragma unroll 8
        for (int e = 0; e < 64; e++) a += no_s[e] * gW[e * 64 + tid];
        float gate = __fdividef(1.f, 1.f + __expf(-a));
        int obp = node * 256 + tid * 4;
        out[obp + 0] = no_s[tid];
        #pragma unroll
        for (int m = 0; m < 3; m++)
            out[obp + 1 + m] = (hti[tid * 3 + m] + htu_s[tid * 3 + m]) * gate;
    }
}

extern "C" void kernel_launch(void* const* d_in, const int* in_sizes, int n_in,
                              void* d_out, int out_size)
{
    const float*         f0    = (const float*)d_in[0];
    const float*         f1    = (const float*)d_in[1];
    const float*         rd    = (const float*)d_in[2];
    const int*           nidx  = (const int*)d_in[3];
    const unsigned char* nmask = (const unsigned char*)d_in[4];
    const float* ln_g = (const float*)d_in[5];
    const float* ln_b = (const float*)d_in[6];
    const float* eW1  = (const float*)d_in[7];
    const float* eb1  = (const float*)d_in[8];
    const float* eW2  = (const float*)d_in[9];
    const float* eb2  = (const float*)d_in[10];
    const float* hW1  = (const float*)d_in[11];
    const float* hb1  = (const float*)d_in[12];
    const float* hW2  = (const float*)d_in[13];
    const float* hb2  = (const float*)d_in[14];
    const float* nW1  = (const float*)d_in[15];
    const float* nb1  = (const float*)d_in[16];
    const float* nW2  = (const float*)d_in[17];
    const float* nb2  = (const float*)d_in[18];
    const float* hns  = (const float*)d_in[19];
    const float* hnb  = (const float*)d_in[20];
    const float* gW   = (const float*)d_in[21];
    const float* gb   = (const float*)d_in[22];
    float* out = (float*)d_out;

    cudaFuncSetAttribute(fused_kernel, cudaFuncAttributeMaxDynamicSharedMemorySize,
                         SMEM_FLOATS * (int)sizeof(float));

    detect_mask_kernel<<<1, 1>>>((const unsigned int*)nmask);
    c01_kernel<<<(B_ * N_) / 128, 512>>>(f0, eW1, eb1);
    fused_kernel<<<B_ * N_, 512, SMEM_FLOATS * sizeof(float)>>>(
        f0, f1, rd, nidx, nmask, ln_g, ln_b, eW1, eW2, eb2, hW1, hb1, hW2, hb2,
        nW1, nb1, nW2, nb2, hns, hnb, gW, gb, out);
}